// round 6
// baseline (speedup 1.0000x reference)
#include <cuda_runtime.h>
#include <math.h>

// Problem shape (fixed by the dataset)
#define BB 16
#define CC 2
#define TT 2000
#define FF 257
#define NCHUNK 50
#define CL 40          // TT / NCHUNK
#define NBLK (BB * NCHUNK)
#define PLANE (TT * FF)

// Scratch (no cudaMalloc allowed). Zero-initialized at load; self-reset at
// end of each run keeps graph replays correct.
__device__ float          g_agg[NBLK * FF];   // chunk-local aggregates
__device__ volatile int   g_flag[NBLK];       // publish flags
__device__ unsigned int   g_vid;              // dynamic block ticket
__device__ unsigned int   g_done;             // completion counter

__device__ __forceinline__ float sqrt_approx(float x) {
    float y; asm("sqrt.approx.f32 %0, %1;" : "=f"(y) : "f"(x)); return y;
}
__device__ __forceinline__ float rcp_approx(float x) {
    float y; asm("rcp.approx.f32 %0, %1;" : "=f"(y) : "f"(x)); return y;
}

__global__ void __launch_bounds__(288, 6)
fused_kernel(const float* __restrict__ in,
             const float* __restrict__ s1,
             const float* __restrict__ weights,
             const float* __restrict__ bias,
             const float* __restrict__ alpha_p,
             float* __restrict__ res,
             float* __restrict__ s_final,
             float* __restrict__ smooth) {
    __shared__ unsigned int s_vid;
    __shared__ int s_last;
    if (threadIdx.x == 0) { s_vid = atomicAdd(&g_vid, 1u); s_last = 0; }
    __syncthreads();
    unsigned int vid = s_vid;
    int b = vid / NCHUNK;
    int chunk = vid % NCHUNK;

    int f = threadIdx.x;
    bool active = (f < FF);
    int fc = active ? f : 0;            // clamp: inactive lanes stay convergent

    float alpha = 1.0f / (1.0f + __expf(-alpha_p[fc]));
    float r = 1.0f - alpha;

    const float2* in0 = (const float2*)in + (size_t)(b * CC + 0) * PLANE;
    int t0 = chunk * CL;

    // ------------- Phase 1: chunk-local scan from 0, double-buffered --------
    float s = 0.0f;
    if (active) {
        const float2* p = in0 + (size_t)t0 * FF + fc;
        float2 cur[8], nxt[8];
#pragma unroll
        for (int j = 0; j < 8; ++j) cur[j] = p[(size_t)j * FF];
#pragma unroll
        for (int g = 0; g < 5; ++g) {                 // 5 groups of 8 = 40
            if (g < 4) {
#pragma unroll
                for (int j = 0; j < 8; ++j)
                    nxt[j] = p[(size_t)((g + 1) * 8 + j) * FF];
            }
#pragma unroll
            for (int j = 0; j < 8; ++j) {
                float d = cur[j].x * cur[j].x + cur[j].y * cur[j].y;
                s = fmaf(r, s, alpha * d);
            }
#pragma unroll
            for (int j = 0; j < 8; ++j) cur[j] = nxt[j];
        }
        g_agg[(size_t)vid * FF + fc] = s;
    }
    __syncthreads();
    __threadfence();
    if (threadIdx.x == 0) g_flag[vid] = 1;            // release

    // ------------- Lookback: parallel spin, then fold -----------------------
    if (threadIdx.x < chunk) {
        int base = b * NCHUNK;
        while (g_flag[base + threadIdx.x] == 0) { }
    }
    __syncthreads();
    __threadfence();                                  // acquire

    float rL = 1.0f;
#pragma unroll
    for (int i = 0; i < CL; ++i) rL *= r;             // r^CL

    float prefix = s1[b * FF + fc];
    {
        const float* agg = g_agg + (size_t)(b * NCHUNK) * FF + fc;
        for (int c = 0; c < chunk; ++c)
            prefix = fmaf(rL, prefix, agg[(size_t)c * FF]);
    }

    // ------------- Phase 3: corrected scan + fused elementwise --------------
    if (active) {
        float w0 = weights[0 * FF + fc], w1 = weights[1 * FF + fc];
        float b0 = bias[0 * FF + fc],    b1 = bias[1 * FF + fc];

        const float2* in1 = (const float2*)in + (size_t)(b * CC + 1) * PLANE;
        float2* res0 = (float2*)res + (size_t)(b * CC + 0) * PLANE;
        float2* res1 = (float2*)res + (size_t)(b * CC + 1) * PLANE;
        float* sm_out = smooth + (size_t)b * PLANE;

        const float2* p0 = in0 + (size_t)t0 * FF + fc;
        const float2* p1 = in1 + (size_t)t0 * FF + fc;

        float sacc = prefix;
        float2 x0[5], x1[5], nx0[5], nx1[5];
#pragma unroll
        for (int j = 0; j < 5; ++j) x0[j] = __ldcs(&p0[(size_t)j * FF]);
#pragma unroll
        for (int j = 0; j < 5; ++j) x1[j] = __ldcs(&p1[(size_t)j * FF]);

#pragma unroll
        for (int g = 0; g < 8; ++g) {                 // 8 groups of 5 = 40
            if (g < 7) {
#pragma unroll
                for (int j = 0; j < 5; ++j)
                    nx0[j] = __ldcs(&p0[(size_t)((g + 1) * 5 + j) * FF]);
#pragma unroll
                for (int j = 0; j < 5; ++j)
                    nx1[j] = __ldcs(&p1[(size_t)((g + 1) * 5 + j) * FF]);
            }
#pragma unroll
            for (int j = 0; j < 5; ++j) {
                size_t idx = (size_t)(t0 + g * 5 + j) * FF + fc;
                float d0 = x0[j].x * x0[j].x + x0[j].y * x0[j].y;
                sacc = fmaf(r, sacc, alpha * d0);
                float sm = sqrt_approx(sacc);
                __stcs(&sm_out[idx], sm);

                float inv0 = w0 * rcp_approx(sm + 1e-8f);
                float m1 = sqrt_approx(x1[j].x * x1[j].x + x1[j].y * x1[j].y);
                float inv1 = w1 * rcp_approx(m1 + 1e-8f);

                __stcs(&res0[idx], make_float2(fmaf(x0[j].x, inv0, b0),
                                               fmaf(x0[j].y, inv0, b0)));
                __stcs(&res1[idx], make_float2(fmaf(x1[j].x, inv1, b1),
                                               fmaf(x1[j].y, inv1, b1)));
            }
#pragma unroll
            for (int j = 0; j < 5; ++j) { x0[j] = nx0[j]; x1[j] = nx1[j]; }
        }
        if (chunk == NCHUNK - 1) s_final[b * FF + fc] = sacc;
    }

    // ------------- Self-reset for next graph replay (parallelized) ----------
    __syncthreads();
    if (threadIdx.x == 0) {
        if (atomicAdd(&g_done, 1u) == NBLK - 1) s_last = 1;
    }
    __syncthreads();
    if (s_last) {
        for (int i = threadIdx.x; i < NBLK; i += blockDim.x) g_flag[i] = 0;
        if (threadIdx.x == 0) { g_vid = 0; g_done = 0; }
        __threadfence();
    }
}

extern "C" void kernel_launch(void* const* d_in, const int* in_sizes, int n_in,
                              void* d_out, int out_size) {
    // metadata order: input, s_1, weights, bias, alpha_param
    const float* in = (const float*)d_in[0];
    const float* s1 = (const float*)d_in[1];
    const float* w  = (const float*)d_in[2];
    const float* bi = (const float*)d_in[3];
    const float* ap = (const float*)d_in[4];

    float* out = (float*)d_out;
    float* res     = out;                                        // [B,C,T,F,2]
    float* s_final = out + (size_t)BB * CC * TT * FF * 2;        // [B,1,F,1]
    float* smooth  = s_final + (size_t)BB * FF;                  // [B,1,T,F,1]

    fused_kernel<<<NBLK, 288>>>(in, s1, w, bi, ap, res, s_final, smooth);
}

// round 7
// speedup vs baseline: 1.3792x; 1.3792x over previous
#include <cuda_runtime.h>
#include <math.h>

// Problem shape (fixed by the dataset)
#define BB 16
#define CC 2
#define TT 2000
#define FF 257
#define NCHUNK 40
#define CL 50                    // TT / NCHUNK
#define NBC (BB * NCHUNK)        // (b, chunk) pairs = 640
#define NBLK (NBC * 2)           // blocks: x2 f-halves = 1280
#define PLANE (TT * FF)
#define HALF0 129                // f-lanes in half 0 (half 1 has 128)

// Scratch (no cudaMalloc allowed). Zero-init at load; self-reset per run.
__device__ float          g_agg[NBC * FF];   // chunk-local aggregates (per f)
__device__ volatile int   g_flag[NBLK];      // publish flags per (b,chunk,half)
__device__ unsigned int   g_vid;             // dynamic block ticket
__device__ unsigned int   g_done;            // completion counter

__device__ __forceinline__ float sqrt_approx(float x) {
    float y; asm("sqrt.approx.f32 %0, %1;" : "=f"(y) : "f"(x)); return y;
}
__device__ __forceinline__ float rcp_approx(float x) {
    float y; asm("rcp.approx.f32 %0, %1;" : "=f"(y) : "f"(x)); return y;
}

__global__ void __launch_bounds__(160, 8)
fused_kernel(const float* __restrict__ in,
             const float* __restrict__ s1,
             const float* __restrict__ weights,
             const float* __restrict__ bias,
             const float* __restrict__ alpha_p,
             float* __restrict__ res,
             float* __restrict__ s_final,
             float* __restrict__ smooth) {
    __shared__ unsigned int s_vid;
    __shared__ int s_last;
    if (threadIdx.x == 0) { s_vid = atomicAdd(&g_vid, 1u); s_last = 0; }
    __syncthreads();
    unsigned int vid = s_vid;

    int half  = vid & 1;
    int bc    = vid >> 1;            // (b, chunk)
    int b     = bc / NCHUNK;
    int chunk = bc % NCHUNK;

    int fbase = half ? HALF0 : 0;
    int cnt   = half ? (FF - HALF0) : HALF0;   // 128 or 129
    int tid   = threadIdx.x;
    bool active = (tid < cnt);
    int f = fbase + (active ? tid : 0);        // clamp: lanes stay convergent

    float alpha = 1.0f / (1.0f + __expf(-alpha_p[f]));
    float r = 1.0f - alpha;

    const float2* in0 = (const float2*)in + (size_t)(b * CC + 0) * PLANE;
    int t0 = chunk * CL;

    // ------------- Phase 1: chunk-local scan from 0 (10-wide batches) -------
    float s = 0.0f;
    if (active) {
        const float2* p = in0 + (size_t)t0 * FF + f;
        for (int tt = 0; tt < CL; tt += 10) {
            float2 x[10];
#pragma unroll
            for (int j = 0; j < 10; ++j) x[j] = p[(size_t)(tt + j) * FF];
#pragma unroll
            for (int j = 0; j < 10; ++j) {
                float d = x[j].x * x[j].x + x[j].y * x[j].y;
                s = fmaf(r, s, alpha * d);
            }
        }
        g_agg[(size_t)bc * FF + f] = s;
    }
    __syncthreads();
    __threadfence();
    if (threadIdx.x == 0) g_flag[vid] = 1;     // release this (chunk, half)

    // ------------- Lookback: parallel spin on predecessors of same half -----
    if (threadIdx.x < chunk) {
        int base = b * NCHUNK;
        while (g_flag[((base + threadIdx.x) << 1) | half] == 0) { }
    }
    __syncthreads();
    __threadfence();                            // acquire

    float rL = 1.0f;
#pragma unroll
    for (int i = 0; i < CL; ++i) rL *= r;       // r^CL

    float prefix = s1[b * FF + f];
    {
        const float* agg = g_agg + (size_t)(b * NCHUNK) * FF + f;
        for (int c = 0; c < chunk; ++c)
            prefix = fmaf(rL, prefix, agg[(size_t)c * FF]);
    }

    // ------------- Phase 3: corrected scan + fused elementwise --------------
    if (active) {
        float w0 = weights[0 * FF + f], w1 = weights[1 * FF + f];
        float b0 = bias[0 * FF + f],    b1 = bias[1 * FF + f];

        const float2* in1 = (const float2*)in + (size_t)(b * CC + 1) * PLANE;
        float2* res0 = (float2*)res + (size_t)(b * CC + 0) * PLANE;
        float2* res1 = (float2*)res + (size_t)(b * CC + 1) * PLANE;
        float* sm_out = smooth + (size_t)b * PLANE;

        const float2* p0 = in0 + (size_t)t0 * FF + f;
        const float2* p1 = in1 + (size_t)t0 * FF + f;

        float sacc = prefix;
        for (int tt = 0; tt < CL; tt += 5) {
            float2 x0[5], x1[5];
#pragma unroll
            for (int j = 0; j < 5; ++j) x0[j] = __ldcs(&p0[(size_t)(tt + j) * FF]);
#pragma unroll
            for (int j = 0; j < 5; ++j) x1[j] = __ldcs(&p1[(size_t)(tt + j) * FF]);
#pragma unroll
            for (int j = 0; j < 5; ++j) {
                size_t idx = (size_t)(t0 + tt + j) * FF + f;
                float d0 = x0[j].x * x0[j].x + x0[j].y * x0[j].y;
                sacc = fmaf(r, sacc, alpha * d0);
                float sm = sqrt_approx(sacc);
                __stcs(&sm_out[idx], sm);

                float inv0 = w0 * rcp_approx(sm + 1e-8f);
                float m1 = sqrt_approx(x1[j].x * x1[j].x + x1[j].y * x1[j].y);
                float inv1 = w1 * rcp_approx(m1 + 1e-8f);

                __stcs(&res0[idx], make_float2(fmaf(x0[j].x, inv0, b0),
                                               fmaf(x0[j].y, inv0, b0)));
                __stcs(&res1[idx], make_float2(fmaf(x1[j].x, inv1, b1),
                                               fmaf(x1[j].y, inv1, b1)));
            }
        }
        if (chunk == NCHUNK - 1) s_final[b * FF + f] = sacc;
    }

    // ------------- Self-reset for next graph replay (parallelized) ----------
    __syncthreads();
    if (threadIdx.x == 0) {
        if (atomicAdd(&g_done, 1u) == NBLK - 1) s_last = 1;
    }
    __syncthreads();
    if (s_last) {
        for (int i = threadIdx.x; i < NBLK; i += blockDim.x) g_flag[i] = 0;
        if (threadIdx.x == 0) { g_vid = 0; g_done = 0; }
        __threadfence();
    }
}

extern "C" void kernel_launch(void* const* d_in, const int* in_sizes, int n_in,
                              void* d_out, int out_size) {
    // metadata order: input, s_1, weights, bias, alpha_param
    const float* in = (const float*)d_in[0];
    const float* s1 = (const float*)d_in[1];
    const float* w  = (const float*)d_in[2];
    const float* bi = (const float*)d_in[3];
    const float* ap = (const float*)d_in[4];

    float* out = (float*)d_out;
    float* res     = out;                                        // [B,C,T,F,2]
    float* s_final = out + (size_t)BB * CC * TT * FF * 2;        // [B,1,F,1]
    float* smooth  = s_final + (size_t)BB * FF;                  // [B,1,T,F,1]

    fused_kernel<<<NBLK, 160>>>(in, s1, w, bi, ap, res, s_final, smooth);
}

// round 8
// speedup vs baseline: 1.6405x; 1.1895x over previous
#include <cuda_runtime.h>
#include <math.h>

// Problem shape (fixed by the dataset)
#define BB 16
#define CC 2
#define TT 2000
#define FF 257
#define NCHUNK 40
#define CL 50                    // TT / NCHUNK
#define NBC (BB * NCHUNK)        // scan work units = 640
#define NBLK (NBC * 2)           // + 640 stream blocks = 1280
#define PLANE (TT * FF)

// Scratch (no cudaMalloc allowed). Zero-init at load; self-reset per run.
__device__ float          g_agg[NBC * FF];   // chunk-local aggregates
__device__ volatile int   g_flag[NBC];       // publish flags per (b,chunk)
__device__ unsigned int   g_vid;             // dynamic block ticket
__device__ unsigned int   g_done;            // completion counter

__device__ __forceinline__ float sqrt_approx(float x) {
    float y; asm("sqrt.approx.f32 %0, %1;" : "=f"(y) : "f"(x)); return y;
}
__device__ __forceinline__ float rcp_approx(float x) {
    float y; asm("rcp.approx.f32 %0, %1;" : "=f"(y) : "f"(x)); return y;
}

__global__ void __launch_bounds__(288, 5)
fused_kernel(const float* __restrict__ in,
             const float* __restrict__ s1,
             const float* __restrict__ weights,
             const float* __restrict__ bias,
             const float* __restrict__ alpha_p,
             float* __restrict__ res,
             float* __restrict__ s_final,
             float* __restrict__ smooth) {
    __shared__ unsigned int s_vid;
    __shared__ int s_last;
    if (threadIdx.x == 0) { s_vid = atomicAdd(&g_vid, 1u); s_last = 0; }
    __syncthreads();
    unsigned int vid = s_vid;

    int is_stream = vid & 1;         // interleave roles so both kinds co-reside
    int bc    = vid >> 1;            // (b, chunk) work unit, 0..639
    int b     = bc / NCHUNK;
    int chunk = bc % NCHUNK;
    int t0    = chunk * CL;

    int tid = threadIdx.x;
    bool active = (tid < FF);
    int f = active ? tid : 0;        // clamp: lanes stay convergent

    if (is_stream) {
        // ================= STREAM ROLE: ch1 elementwise only =================
        if (active) {
            float w1 = weights[1 * FF + f];
            float b1 = bias[1 * FF + f];
            const float2* p1 = (const float2*)in + (b * CC + 1) * PLANE + t0 * FF + f;
            float2*       r1 = (float2*)res      + (b * CC + 1) * PLANE + t0 * FF + f;
            for (int tt = 0; tt < CL; tt += 10) {
                float2 x[10];
#pragma unroll
                for (int j = 0; j < 10; ++j) x[j] = __ldcs(&p1[j * FF]);
#pragma unroll
                for (int j = 0; j < 10; ++j) {
                    float m = sqrt_approx(x[j].x * x[j].x + x[j].y * x[j].y);
                    float inv = w1 * rcp_approx(m + 1e-8f);
                    __stcs(&r1[j * FF], make_float2(fmaf(x[j].x, inv, b1),
                                                    fmaf(x[j].y, inv, b1)));
                }
                p1 += 10 * FF;
                r1 += 10 * FF;
            }
        }
    } else {
        // ================= SCAN ROLE: ch0 scan + smooth + res0 ===============
        float alpha = 1.0f / (1.0f + __expf(-alpha_p[f]));
        float r = 1.0f - alpha;

        const float2* in0 = (const float2*)in + (b * CC + 0) * PLANE;

        // ---- Phase 1: chunk-local scan from 0 (10-wide batches) ----
        float s = 0.0f;
        if (active) {
            const float2* p = in0 + t0 * FF + f;
            for (int tt = 0; tt < CL; tt += 10) {
                float2 x[10];
#pragma unroll
                for (int j = 0; j < 10; ++j) x[j] = p[j * FF];
#pragma unroll
                for (int j = 0; j < 10; ++j) {
                    float d = x[j].x * x[j].x + x[j].y * x[j].y;
                    s = fmaf(r, s, alpha * d);
                }
                p += 10 * FF;
            }
            g_agg[bc * FF + f] = s;
        }
        __syncthreads();
        __threadfence();
        if (threadIdx.x == 0) g_flag[bc] = 1;      // release

        // ---- Lookback: parallel spin, then fold ----
        if (threadIdx.x < chunk) {
            int base = b * NCHUNK;
            while (g_flag[base + threadIdx.x] == 0) { }
        }
        __syncthreads();
        __threadfence();                            // acquire

        float rL = 1.0f;
#pragma unroll
        for (int i = 0; i < CL; ++i) rL *= r;       // r^CL

        float prefix = s1[b * FF + f];
        {
            const float* agg = g_agg + (b * NCHUNK) * FF + f;
            for (int c = 0; c < chunk; ++c)
                prefix = fmaf(rL, prefix, agg[c * FF]);
        }

        // ---- Phase 3: corrected scan (ch0 re-read is block-local L2-hot) ----
        if (active) {
            float w0 = weights[0 * FF + f];
            float b0 = bias[0 * FF + f];

            const float2* p0 = in0 + t0 * FF + f;
            float2* r0 = (float2*)res + (b * CC + 0) * PLANE + t0 * FF + f;
            float*  sm = smooth + b * PLANE + t0 * FF + f;

            float sacc = prefix;
            for (int tt = 0; tt < CL; tt += 10) {
                float2 x[10];
#pragma unroll
                for (int j = 0; j < 10; ++j) x[j] = __ldcs(&p0[j * FF]);
#pragma unroll
                for (int j = 0; j < 10; ++j) {
                    float d = x[j].x * x[j].x + x[j].y * x[j].y;
                    sacc = fmaf(r, sacc, alpha * d);
                    float smv = sqrt_approx(sacc);
                    __stcs(&sm[j * FF], smv);
                    float inv = w0 * rcp_approx(smv + 1e-8f);
                    __stcs(&r0[j * FF], make_float2(fmaf(x[j].x, inv, b0),
                                                    fmaf(x[j].y, inv, b0)));
                }
                p0 += 10 * FF;
                r0 += 10 * FF;
                sm += 10 * FF;
            }
            if (chunk == NCHUNK - 1) s_final[b * FF + f] = sacc;
        }
    }

    // ---- Self-reset for next graph replay (parallelized) ----
    __syncthreads();
    if (threadIdx.x == 0) {
        if (atomicAdd(&g_done, 1u) == NBLK - 1) s_last = 1;
    }
    __syncthreads();
    if (s_last) {
        for (int i = threadIdx.x; i < NBC; i += blockDim.x) g_flag[i] = 0;
        if (threadIdx.x == 0) { g_vid = 0; g_done = 0; }
        __threadfence();
    }
}

extern "C" void kernel_launch(void* const* d_in, const int* in_sizes, int n_in,
                              void* d_out, int out_size) {
    // metadata order: input, s_1, weights, bias, alpha_param
    const float* in = (const float*)d_in[0];
    const float* s1 = (const float*)d_in[1];
    const float* w  = (const float*)d_in[2];
    const float* bi = (const float*)d_in[3];
    const float* ap = (const float*)d_in[4];

    float* out = (float*)d_out;
    float* res     = out;                                        // [B,C,T,F,2]
    float* s_final = out + (size_t)BB * CC * TT * FF * 2;        // [B,1,F,1]
    float* smooth  = s_final + (size_t)BB * FF;                  // [B,1,T,F,1]

    fused_kernel<<<NBLK, 288>>>(in, s1, w, bi, ap, res, s_final, smooth);
}